// round 12
// baseline (speedup 1.0000x reference)
#include <cuda_runtime.h>
#include <cuda_fp16.h>
#include <mma.h>
#include <stdint.h>

using namespace nvcuda;

// Problem constants
#define NN 262144
#define EE (NN * 16)
#define CC 64
#define NVOXD 20
#define NVOX 8000
#define BN_EPS 1e-5f
#define GRID_INV 2.0f   // 1/0.5
#define FULLMASK 0xFFFFFFFFu
#define MAXDEG 64

typedef unsigned long long ull;
typedef long long ll;

// -------- scratch (all load-time zero; out_kernel re-zeroes accumulators each replay) ----
__device__ __half g_hh[NN * CC];          // h = x@W+b in fp16
__device__ float g_colsum[CC];
__device__ float g_colsq[CC];
__device__ float g_scale[CC];
__device__ float g_shift[CC];
__device__ int   g_negflag;               // any(scale<0)?
__device__ float g_xsum[NVOX * CC];
__device__ float g_psum[NVOX * 3];
__device__ float g_cnt[NVOX];
__device__ int   g_cnt_i[NN];             // in-degree
__device__ int   g_adj[NN * MAXDEG + 4];  // fixed-capacity buckets

// ======================= STREAM A: wmma GEMM + stats (fp16 out) =======================
#define XS 80
#define WS 80
#define CSO 72
#define SM_X_BYTES (128 * XS * 2)
#define SM_W_OFF   SM_X_BYTES
#define SM_C_BYTES (128 * CSO * 4)
#define SM_RED_OFF SM_C_BYTES
#define GS_SMEM_BYTES (SM_C_BYTES + 512)

__global__ __launch_bounds__(256) void gemm_stats_kernel(const float* __restrict__ x,
                                                         const float* __restrict__ W,
                                                         const float* __restrict__ b) {
    extern __shared__ char smc[];
    __half* xs  = reinterpret_cast<__half*>(smc);
    __half* Wsf = reinterpret_cast<__half*>(smc + SM_W_OFF);
    float*  Cs  = reinterpret_cast<float*>(smc);
    float*  red = reinterpret_cast<float*>(smc + SM_RED_OFF);
    int tid = threadIdx.x;
    int row0 = blockIdx.x * 128;

#pragma unroll
    for (int i = tid; i < 2048; i += 256) {
        int row = i >> 4, c4 = (i & 15) * 4;
        float4 v = __ldcs(&reinterpret_cast<const float4*>(x + (ll)(row0 + row) * 64)[i & 15]);
        __half2 lo = __floats2half2_rn(v.x, v.y);
        __half2 hi = __floats2half2_rn(v.z, v.w);
        uint2 p;
        p.x = *reinterpret_cast<unsigned*>(&lo);
        p.y = *reinterpret_cast<unsigned*>(&hi);
        *reinterpret_cast<uint2*>(&xs[row * XS + c4]) = p;
    }
#pragma unroll
    for (int i = tid; i < 1024; i += 256) {
        int row = i >> 4, c4 = (i & 15) * 4;
        float4 v = reinterpret_cast<const float4*>(W)[i];
        __half2 lo = __floats2half2_rn(v.x, v.y);
        __half2 hi = __floats2half2_rn(v.z, v.w);
        uint2 p;
        p.x = *reinterpret_cast<unsigned*>(&lo);
        p.y = *reinterpret_cast<unsigned*>(&hi);
        *reinterpret_cast<uint2*>(&Wsf[row * WS + c4]) = p;
    }
    __syncthreads();

    int w = tid >> 5;
    wmma::fragment<wmma::accumulator, 16, 16, 16, float> acc[4];
#pragma unroll
    for (int n = 0; n < 4; n++) wmma::fill_fragment(acc[n], 0.0f);
#pragma unroll
    for (int k = 0; k < 4; k++) {
        wmma::fragment<wmma::matrix_a, 16, 16, 16, __half, wmma::row_major> af;
        wmma::load_matrix_sync(af, xs + (16 * w) * XS + 16 * k, XS);
#pragma unroll
        for (int n = 0; n < 4; n++) {
            wmma::fragment<wmma::matrix_b, 16, 16, 16, __half, wmma::row_major> bf;
            wmma::load_matrix_sync(bf, Wsf + (16 * k) * WS + 16 * n, WS);
            wmma::mma_sync(acc[n], af, bf, acc[n]);
        }
    }
    __syncthreads();

#pragma unroll
    for (int n = 0; n < 4; n++)
        wmma::store_matrix_sync(Cs + (16 * w) * CSO + 16 * n, acc[n], CSO, wmma::mem_row_major);
    if (tid < 128) red[tid] = 0.f;
    __syncthreads();

    int cp = tid & 31;
    int rg = tid >> 5;
    float b0 = b[2 * cp], b1 = b[2 * cp + 1];
    float s0 = 0.f, q0 = 0.f, s1 = 0.f, q1 = 0.f;
    unsigned* hout = reinterpret_cast<unsigned*>(g_hh);
#pragma unroll
    for (int rr = 0; rr < 16; rr++) {
        int row = 16 * rg + rr;
        float2 v = *reinterpret_cast<float2*>(&Cs[row * CSO + 2 * cp]);
        float v0 = v.x + b0, v1 = v.y + b1;
        __half2 h2 = __floats2half2_rn(v0, v1);
        hout[(ll)(row0 + row) * 32 + cp] = *reinterpret_cast<unsigned*>(&h2);
        s0 += v0; q0 += v0 * v0; s1 += v1; q1 += v1 * v1;
    }
    atomicAdd(&red[2 * cp], s0);      atomicAdd(&red[2 * cp + 1], s1);
    atomicAdd(&red[64 + 2 * cp], q0); atomicAdd(&red[64 + 2 * cp + 1], q1);
    __syncthreads();
    if (tid < 64) {
        atomicAdd(&g_colsum[tid], red[tid]);
        atomicAdd(&g_colsq[tid],  red[64 + tid]);
    }
}

// -------- A2: fold BN into scale/shift; detect negative scales; reset stats --------
__global__ void scale_kernel(const float* __restrict__ gamma, const float* __restrict__ beta) {
    __shared__ int flag;
    int c = threadIdx.x;
    if (c == 0) flag = 0;
    __syncthreads();
    if (c < CC) {
        float mean = g_colsum[c] * (1.0f / NN);
        float var = g_colsq[c] * (1.0f / NN) - mean * mean;
        float sc = gamma[c] * rsqrtf(var + BN_EPS);
        g_scale[c] = sc;
        g_shift[c] = beta[c] - mean * sc;
        g_colsum[c] = 0.f;
        g_colsq[c] = 0.f;
        if (sc < 0.f) flag = 1;
    }
    __syncthreads();
    if (c == 0) g_negflag = flag;
}

// ================= STREAM B: single-kernel bucket build =================
__global__ __launch_bounds__(256) void scatter_kernel(const int* __restrict__ ei) {
    int e = blockIdx.x * blockDim.x + threadIdx.x;
    int row = __ldcs(&ei[e]);
    int col = __ldcs(&ei[EE + e]);
    int p = atomicAdd(&g_cnt_i[col], 1);
    if (p < MAXDEG) g_adj[col * MAXDEG + p] = row;
}

// ======================= JOINED: gather (2-node ILP) -> out =======================
// 8 lanes per NODE PAIR: lane handles 8 channels (uint4) of nodes 2p and 2p+1.
// 8 independent row loads per chunk -> 2x MLP vs single-node version. Bucket chunk
// reads (<=16 int4) are always in-bounds; selects discard entries beyond cnt.
__global__ __launch_bounds__(256, 4) void gather_kernel(const float* __restrict__ pos) {
    int pair = (blockIdx.x * blockDim.x + threadIdx.x) >> 3;
    int nA = 2 * pair, nB = 2 * pair + 1;
    int l = threadIdx.x & 7;
    int base8 = threadIdx.x & 24;
    unsigned int m8 = 0xFFu << base8;

    int cntA = min(g_cnt_i[nA], MAXDEG);
    int cntB = min(g_cnt_i[nB], MAXDEG);
    const int4* bktA = reinterpret_cast<const int4*>(&g_adj[(ll)nA * MAXDEG]);
    const int4* bktB = reinterpret_cast<const int4*>(&g_adj[(ll)nB * MAXDEG]);

    float pA0 = 0.f, pA1 = 0.f, pA2 = 0.f, pB0 = 0.f, pB1 = 0.f, pB2 = 0.f;
    if (l == 0) {
        const float* pp = pos + (ll)pair * 6;
        pA0 = pp[0]; pA1 = pp[1]; pA2 = pp[2];
        pB0 = pp[3]; pB1 = pp[4]; pB2 = pp[5];
    }
    const uint4* h8 = reinterpret_cast<const uint4*>(g_hh);
    uint4 selfA = __ldg(&h8[(ll)nA * 8 + l]);
    uint4 selfB = __ldg(&h8[(ll)nB * 8 + l]);

    __half2 xA0 = *reinterpret_cast<__half2*>(&selfA.x);
    __half2 xA1 = *reinterpret_cast<__half2*>(&selfA.y);
    __half2 xA2 = *reinterpret_cast<__half2*>(&selfA.z);
    __half2 xA3 = *reinterpret_cast<__half2*>(&selfA.w);
    __half2 xB0 = *reinterpret_cast<__half2*>(&selfB.x);
    __half2 xB1 = *reinterpret_cast<__half2*>(&selfB.y);
    __half2 xB2 = *reinterpret_cast<__half2*>(&selfB.z);
    __half2 xB3 = *reinterpret_cast<__half2*>(&selfB.w);
    __half2 nA0 = xA0, nA1 = xA1, nA2 = xA2, nA3 = xA3;
    __half2 nB0 = xB0, nB1 = xB1, nB2 = xB2, nB3 = xB3;

    int voxA = 0, voxB = 0;
    if (l == 0) {
        int vx = min(max((int)floorf(pA0 * GRID_INV), 0), NVOXD - 1);
        int vy = min(max((int)floorf(pA1 * GRID_INV), 0), NVOXD - 1);
        int vz = min(max((int)floorf(pA2 * GRID_INV), 0), NVOXD - 1);
        voxA = (vx * NVOXD + vy) * NVOXD + vz;
        vx = min(max((int)floorf(pB0 * GRID_INV), 0), NVOXD - 1);
        vy = min(max((int)floorf(pB1 * GRID_INV), 0), NVOXD - 1);
        vz = min(max((int)floorf(pB2 * GRID_INV), 0), NVOXD - 1);
        voxB = (vx * NVOXD + vy) * NVOXD + vz;
    }
    voxA = __shfl_sync(m8, voxA, base8);
    voxB = __shfl_sync(m8, voxB, base8);

    int neg = g_negflag;
    int nbmax = (max(cntA, cntB) + 3) >> 2;

#define GATH_BODY(DOMIN)                                                        \
    for (int c = 0; c < nbmax; c++) {                                           \
        int4 qA = __ldg(&bktA[c]);                                              \
        int4 qB = __ldg(&bktB[c]);                                              \
        int j0 = 4 * c;                                                         \
        int a0i = (j0 + 0 < cntA) ? qA.x : nA;                                  \
        int a1i = (j0 + 1 < cntA) ? qA.y : nA;                                  \
        int a2i = (j0 + 2 < cntA) ? qA.z : nA;                                  \
        int a3i = (j0 + 3 < cntA) ? qA.w : nA;                                  \
        int b0i = (j0 + 0 < cntB) ? qB.x : nB;                                  \
        int b1i = (j0 + 1 < cntB) ? qB.y : nB;                                  \
        int b2i = (j0 + 2 < cntB) ? qB.z : nB;                                  \
        int b3i = (j0 + 3 < cntB) ? qB.w : nB;                                  \
        uint4 uA0 = __ldg(&h8[(ll)a0i * 8 + l]);                                \
        uint4 uA1 = __ldg(&h8[(ll)a1i * 8 + l]);                                \
        uint4 uA2 = __ldg(&h8[(ll)a2i * 8 + l]);                                \
        uint4 uA3 = __ldg(&h8[(ll)a3i * 8 + l]);                                \
        uint4 uB0 = __ldg(&h8[(ll)b0i * 8 + l]);                                \
        uint4 uB1 = __ldg(&h8[(ll)b1i * 8 + l]);                                \
        uint4 uB2 = __ldg(&h8[(ll)b2i * 8 + l]);                                \
        uint4 uB3 = __ldg(&h8[(ll)b3i * 8 + l]);                                \
        const uint4* ua[4] = {&uA0, &uA1, &uA2, &uA3};                          \
        const uint4* ub[4] = {&uB0, &uB1, &uB2, &uB3};                          \
        _Pragma("unroll")                                                       \
        for (int t = 0; t < 4; t++) {                                           \
            __half2 c0 = *reinterpret_cast<const __half2*>(&ua[t]->x);          \
            __half2 c1 = *reinterpret_cast<const __half2*>(&ua[t]->y);          \
            __half2 c2 = *reinterpret_cast<const __half2*>(&ua[t]->z);          \
            __half2 c3 = *reinterpret_cast<const __half2*>(&ua[t]->w);          \
            xA0 = __hmax2(xA0, c0); xA1 = __hmax2(xA1, c1);                     \
            xA2 = __hmax2(xA2, c2); xA3 = __hmax2(xA3, c3);                     \
            if (DOMIN) {                                                        \
                nA0 = __hmin2(nA0, c0); nA1 = __hmin2(nA1, c1);                 \
                nA2 = __hmin2(nA2, c2); nA3 = __hmin2(nA3, c3);                 \
            }                                                                   \
            __half2 d0 = *reinterpret_cast<const __half2*>(&ub[t]->x);          \
            __half2 d1 = *reinterpret_cast<const __half2*>(&ub[t]->y);          \
            __half2 d2 = *reinterpret_cast<const __half2*>(&ub[t]->z);          \
            __half2 d3 = *reinterpret_cast<const __half2*>(&ub[t]->w);          \
            xB0 = __hmax2(xB0, d0); xB1 = __hmax2(xB1, d1);                     \
            xB2 = __hmax2(xB2, d2); xB3 = __hmax2(xB3, d3);                     \
            if (DOMIN) {                                                        \
                nB0 = __hmin2(nB0, d0); nB1 = __hmin2(nB1, d1);                 \
                nB2 = __hmin2(nB2, d2); nB3 = __hmin2(nB3, d3);                 \
            }                                                                   \
        }                                                                       \
    }

    if (!neg) { GATH_BODY(0) } else { GATH_BODY(1) }
#undef GATH_BODY

    float4 sca = *reinterpret_cast<const float4*>(&g_scale[8 * l]);
    float4 scb = *reinterpret_cast<const float4*>(&g_scale[8 * l + 4]);
    float4 sha = *reinterpret_cast<const float4*>(&g_shift[8 * l]);
    float4 shb = *reinterpret_cast<const float4*>(&g_shift[8 * l + 4]);

#define BN_FIN(res, mx, mn, sc, sh)                                             \
    do {                                                                        \
        float2 fx = __half22float2(mx);                                         \
        if (!neg) {                                                             \
            res[0] = fmaxf(fmaf(fx.x, sc##x, sh##x), 0.f);                      \
            res[1] = fmaxf(fmaf(fx.y, sc##y, sh##y), 0.f);                      \
        } else {                                                                \
            float2 fn = __half22float2(mn);                                     \
            res[0] = fmaxf(fmaxf(fmaf(fx.x, sc##x, sh##x),                      \
                                 fmaf(fn.x, sc##x, sh##x)), 0.f);               \
            res[1] = fmaxf(fmaxf(fmaf(fx.y, sc##y, sh##y),                      \
                                 fmaf(fn.y, sc##y, sh##y)), 0.f);               \
        }                                                                       \
    } while (0)

    float rA[8], rB[8];
    {
        float scx = sca.x, scy = sca.y, shx = sha.x, shy = sha.y;
        BN_FIN((rA + 0), xA0, nA0, sc, sh); BN_FIN((rB + 0), xB0, nB0, sc, sh);
        scx = sca.z; scy = sca.w; shx = sha.z; shy = sha.w;
        BN_FIN((rA + 2), xA1, nA1, sc, sh); BN_FIN((rB + 2), xB1, nB1, sc, sh);
        scx = scb.x; scy = scb.y; shx = shb.x; shy = shb.y;
        BN_FIN((rA + 4), xA2, nA2, sc, sh); BN_FIN((rB + 4), xB2, nB2, sc, sh);
        scx = scb.z; scy = scb.w; shx = shb.z; shy = shb.w;
        BN_FIN((rA + 6), xA3, nA3, sc, sh); BN_FIN((rB + 6), xB3, nB3, sc, sh);
    }
#undef BN_FIN

    float* xbA = &g_xsum[(ll)voxA * 64 + 8 * l];
    float* xbB = &g_xsum[(ll)voxB * 64 + 8 * l];
    asm volatile("red.global.add.v4.f32 [%0], {%1, %2, %3, %4};"
                 :: "l"(xbA), "f"(rA[0]), "f"(rA[1]), "f"(rA[2]), "f"(rA[3]) : "memory");
    asm volatile("red.global.add.v4.f32 [%0], {%1, %2, %3, %4};"
                 :: "l"(xbA + 4), "f"(rA[4]), "f"(rA[5]), "f"(rA[6]), "f"(rA[7]) : "memory");
    asm volatile("red.global.add.v4.f32 [%0], {%1, %2, %3, %4};"
                 :: "l"(xbB), "f"(rB[0]), "f"(rB[1]), "f"(rB[2]), "f"(rB[3]) : "memory");
    asm volatile("red.global.add.v4.f32 [%0], {%1, %2, %3, %4};"
                 :: "l"(xbB + 4), "f"(rB[4]), "f"(rB[5]), "f"(rB[6]), "f"(rB[7]) : "memory");
    if (l == 0) {
        atomicAdd(&g_cnt[voxA], 1.0f);
        atomicAdd(&g_psum[voxA * 3 + 0], pA0);
        atomicAdd(&g_psum[voxA * 3 + 1], pA1);
        atomicAdd(&g_psum[voxA * 3 + 2], pA2);
        atomicAdd(&g_cnt[voxB], 1.0f);
        atomicAdd(&g_psum[voxB * 3 + 0], pB0);
        atomicAdd(&g_psum[voxB * 3 + 1], pB1);
        atomicAdd(&g_psum[voxB * 3 + 2], pB2);
    }
}

// -------- finalize output [NVOX, 67] AND self-clean all accumulators for next replay ----
__global__ __launch_bounds__(256) void out_kernel(float* __restrict__ out) {
    int gid = blockIdx.x * blockDim.x + threadIdx.x;     // 262144 threads
    g_cnt_i[gid] = 0;

    int vox = gid >> 5;
    int lane = gid & 31;
    if (vox >= NVOX) return;

    float cntv = g_cnt[vox];
    float inv = 1.0f / fmaxf(cntv, 1.0f);

    float v0 = g_xsum[vox * 64 + lane];
    float v1 = g_xsum[vox * 64 + 32 + lane];
    float p = (lane < 3) ? g_psum[vox * 3 + lane] : 0.f;

    out[(ll)vox * 67 + lane] = v0 * inv;
    out[(ll)vox * 67 + 32 + lane] = v1 * inv;
    if (lane < 3) out[(ll)vox * 67 + 64 + lane] = p * inv;

    __syncwarp();
    g_xsum[vox * 64 + lane] = 0.f;
    g_xsum[vox * 64 + 32 + lane] = 0.f;
    if (lane < 3) g_psum[vox * 3 + lane] = 0.f;
    if (lane == 0) g_cnt[vox] = 0.f;
}

extern "C" void kernel_launch(void* const* d_in, const int* in_sizes, int n_in,
                              void* d_out, int out_size) {
    const float* x     = (const float*)d_in[0];  // [N, 64]
    const float* pos   = (const float*)d_in[1];  // [N, 3]
    const int*   ei    = (const int*)d_in[2];    // [2, E]
    const float* W     = (const float*)d_in[3];  // [64, 64]
    const float* b     = (const float*)d_in[4];  // [64]
    const float* gamma = (const float*)d_in[5];  // [64]
    const float* beta  = (const float*)d_in[6];  // [64]
    float* out = (float*)d_out;                  // [8000, 67]

    static cudaStream_t sB = nullptr;
    static cudaEvent_t evFork = nullptr, evJoin = nullptr;
    if (sB == nullptr) {
        cudaStreamCreateWithFlags(&sB, cudaStreamNonBlocking);
        cudaEventCreateWithFlags(&evFork, cudaEventDisableTiming);
        cudaEventCreateWithFlags(&evJoin, cudaEventDisableTiming);
    }

    cudaEventRecord(evFork, 0);
    cudaStreamWaitEvent(sB, evFork, 0);

    scatter_kernel<<<EE / 256, 256, 0, sB>>>(ei);                  // 1 (B)
    cudaEventRecord(evJoin, sB);

    gemm_stats_kernel<<<NN / 128, 256, GS_SMEM_BYTES>>>(x, W, b);  // 2 (0)
    scale_kernel<<<1, 64>>>(gamma, beta);                          // 3 (0)

    cudaStreamWaitEvent(0, evJoin, 0);
    gather_kernel<<<NN * 4 / 256, 256>>>(pos);                     // 4 (0) <- ncu slot
    out_kernel<<<NN / 256, 256>>>(out);                            // 5 (0)
}

// round 13
// speedup vs baseline: 1.0006x; 1.0006x over previous
#include <cuda_runtime.h>
#include <cuda_fp16.h>
#include <mma.h>
#include <stdint.h>

using namespace nvcuda;

// Problem constants
#define NN 262144
#define EE (NN * 16)
#define CC 64
#define NVOXD 20
#define NVOX 8000
#define BN_EPS 1e-5f
#define GRID_INV 2.0f   // 1/0.5
#define FULLMASK 0xFFFFFFFFu
#define MAXDEG 64

typedef unsigned long long ull;
typedef long long ll;

// -------- scratch (all load-time zero; out_kernel re-zeroes accumulators each replay) ----
__device__ __half g_hh[NN * CC];          // h = x@W+b in fp16
__device__ float g_colsum[CC];
__device__ float g_colsq[CC];
__device__ float g_scale[CC];
__device__ float g_shift[CC];
__device__ int   g_negflag;               // any(scale<0)?
__device__ float g_xsum[NVOX * CC];
__device__ float g_psum[NVOX * 3];
__device__ float g_cnt[NVOX];
__device__ int   g_cnt_i[NN];             // in-degree
__device__ int   g_adj[NN * MAXDEG + 4];  // fixed-capacity buckets

// ======================= FAT kernel: wmma GEMM+stats blocks + scatter blocks =======================
// 18432 blocks: blockIdx%9==0 -> GEMM block (2048 of them), else scatter block (16384).
// Interleaving co-schedules both workloads on every SM: GEMM is tensor/smem/DRAM-read
// bound, scatter is L2-atomic bound -> near-disjoint resources.
#define XS 80
#define WS 80
#define CSO 72
#define SM_X_BYTES (128 * XS * 2)
#define SM_W_OFF   SM_X_BYTES
#define SM_C_BYTES (128 * CSO * 4)
#define SM_RED_OFF SM_C_BYTES
#define GS_SMEM_BYTES (SM_C_BYTES + 512)
#define GEMM_BLOCKS (NN / 128)            // 2048
#define SCAT_BLOCKS (EE / 256)            // 16384
#define FAT_BLOCKS (GEMM_BLOCKS + SCAT_BLOCKS)   // 18432 = 2048*9

__device__ __forceinline__ void gemm_body(int gb, const float* __restrict__ x,
                                          const float* __restrict__ W,
                                          const float* __restrict__ b,
                                          char* smc) {
    __half* xs  = reinterpret_cast<__half*>(smc);
    __half* Wsf = reinterpret_cast<__half*>(smc + SM_W_OFF);
    float*  Cs  = reinterpret_cast<float*>(smc);
    float*  red = reinterpret_cast<float*>(smc + SM_RED_OFF);
    int tid = threadIdx.x;
    int row0 = gb * 128;

#pragma unroll
    for (int i = tid; i < 2048; i += 256) {
        int row = i >> 4, c4 = (i & 15) * 4;
        float4 v = __ldcs(&reinterpret_cast<const float4*>(x + (ll)(row0 + row) * 64)[i & 15]);
        __half2 lo = __floats2half2_rn(v.x, v.y);
        __half2 hi = __floats2half2_rn(v.z, v.w);
        uint2 p;
        p.x = *reinterpret_cast<unsigned*>(&lo);
        p.y = *reinterpret_cast<unsigned*>(&hi);
        *reinterpret_cast<uint2*>(&xs[row * XS + c4]) = p;
    }
#pragma unroll
    for (int i = tid; i < 1024; i += 256) {
        int row = i >> 4, c4 = (i & 15) * 4;
        float4 v = reinterpret_cast<const float4*>(W)[i];
        __half2 lo = __floats2half2_rn(v.x, v.y);
        __half2 hi = __floats2half2_rn(v.z, v.w);
        uint2 p;
        p.x = *reinterpret_cast<unsigned*>(&lo);
        p.y = *reinterpret_cast<unsigned*>(&hi);
        *reinterpret_cast<uint2*>(&Wsf[row * WS + c4]) = p;
    }
    __syncthreads();

    int w = tid >> 5;
    wmma::fragment<wmma::accumulator, 16, 16, 16, float> acc[4];
#pragma unroll
    for (int n = 0; n < 4; n++) wmma::fill_fragment(acc[n], 0.0f);
#pragma unroll
    for (int k = 0; k < 4; k++) {
        wmma::fragment<wmma::matrix_a, 16, 16, 16, __half, wmma::row_major> af;
        wmma::load_matrix_sync(af, xs + (16 * w) * XS + 16 * k, XS);
#pragma unroll
        for (int n = 0; n < 4; n++) {
            wmma::fragment<wmma::matrix_b, 16, 16, 16, __half, wmma::row_major> bf;
            wmma::load_matrix_sync(bf, Wsf + (16 * k) * WS + 16 * n, WS);
            wmma::mma_sync(acc[n], af, bf, acc[n]);
        }
    }
    __syncthreads();

#pragma unroll
    for (int n = 0; n < 4; n++)
        wmma::store_matrix_sync(Cs + (16 * w) * CSO + 16 * n, acc[n], CSO, wmma::mem_row_major);
    if (tid < 128) red[tid] = 0.f;
    __syncthreads();

    int cp = tid & 31;
    int rg = tid >> 5;
    float b0 = b[2 * cp], b1 = b[2 * cp + 1];
    float s0 = 0.f, q0 = 0.f, s1 = 0.f, q1 = 0.f;
    unsigned* hout = reinterpret_cast<unsigned*>(g_hh);
#pragma unroll
    for (int rr = 0; rr < 16; rr++) {
        int row = 16 * rg + rr;
        float2 v = *reinterpret_cast<float2*>(&Cs[row * CSO + 2 * cp]);
        float v0 = v.x + b0, v1 = v.y + b1;
        __half2 h2 = __floats2half2_rn(v0, v1);
        hout[(ll)(row0 + row) * 32 + cp] = *reinterpret_cast<unsigned*>(&h2);
        s0 += v0; q0 += v0 * v0; s1 += v1; q1 += v1 * v1;
    }
    atomicAdd(&red[2 * cp], s0);      atomicAdd(&red[2 * cp + 1], s1);
    atomicAdd(&red[64 + 2 * cp], q0); atomicAdd(&red[64 + 2 * cp + 1], q1);
    __syncthreads();
    if (tid < 64) {
        atomicAdd(&g_colsum[tid], red[tid]);
        atomicAdd(&g_colsq[tid],  red[64 + tid]);
    }
}

__device__ __forceinline__ void scatter_body(int sb, const int* __restrict__ ei) {
    int e = sb * 256 + threadIdx.x;
    int row = __ldcs(&ei[e]);
    int col = __ldcs(&ei[EE + e]);
    int p = atomicAdd(&g_cnt_i[col], 1);
    if (p < MAXDEG) g_adj[col * MAXDEG + p] = row;
}

__global__ __launch_bounds__(256) void fat_kernel(const float* __restrict__ x,
                                                  const float* __restrict__ W,
                                                  const float* __restrict__ b,
                                                  const int* __restrict__ ei) {
    extern __shared__ char smc[];
    int r = blockIdx.x % 9;
    int g = blockIdx.x / 9;
    if (r == 0) gemm_body(g, x, W, b, smc);
    else        scatter_body(g * 8 + (r - 1), ei);
}

// -------- fold BN into scale/shift; detect negative scales; reset stats --------
__global__ void scale_kernel(const float* __restrict__ gamma, const float* __restrict__ beta) {
    __shared__ int flag;
    int c = threadIdx.x;
    if (c == 0) flag = 0;
    __syncthreads();
    if (c < CC) {
        float mean = g_colsum[c] * (1.0f / NN);
        float var = g_colsq[c] * (1.0f / NN) - mean * mean;
        float sc = gamma[c] * rsqrtf(var + BN_EPS);
        g_scale[c] = sc;
        g_shift[c] = beta[c] - mean * sc;
        g_colsum[c] = 0.f;
        g_colsq[c] = 0.f;
        if (sc < 0.f) flag = 1;
    }
    __syncthreads();
    if (c == 0) g_negflag = flag;
}

// ======================= gather (R11 form, half-grid) -> out =======================
// 8 lanes per node; lane handles 8 channels (uint4). Neighbor indices from uniform
// int4 loads, prefetched one chunk ahead; bounds handled by selects.
__global__ __launch_bounds__(256, 5) void gather_kernel(const float* __restrict__ pos, int node0) {
    int node = node0 + ((blockIdx.x * blockDim.x + threadIdx.x) >> 3);
    int l = threadIdx.x & 7;
    int base8 = threadIdx.x & 24;
    unsigned int m8 = 0xFFu << base8;

    int cnt = min(g_cnt_i[node], MAXDEG);
    const int4* bucket4 = reinterpret_cast<const int4*>(&g_adj[(ll)node * MAXDEG]);
    float px = 0.f, py = 0.f, pz = 0.f;
    if (l == 0) {
        px = pos[node * 3 + 0];
        py = pos[node * 3 + 1];
        pz = pos[node * 3 + 2];
    }
    const uint4* h8 = reinterpret_cast<const uint4*>(g_hh);
    uint4 self = __ldg(&h8[(ll)node * 8 + l]);

    __half2 mx0 = *reinterpret_cast<__half2*>(&self.x);
    __half2 mx1 = *reinterpret_cast<__half2*>(&self.y);
    __half2 mx2 = *reinterpret_cast<__half2*>(&self.z);
    __half2 mx3 = *reinterpret_cast<__half2*>(&self.w);
    __half2 mn0 = mx0, mn1 = mx1, mn2 = mx2, mn3 = mx3;

    int vox = 0;
    if (l == 0) {
        int vx = min(max((int)floorf(px * GRID_INV), 0), NVOXD - 1);
        int vy = min(max((int)floorf(py * GRID_INV), 0), NVOXD - 1);
        int vz = min(max((int)floorf(pz * GRID_INV), 0), NVOXD - 1);
        vox = (vx * NVOXD + vy) * NVOXD + vz;
    }
    vox = __shfl_sync(m8, vox, base8);

    int neg = g_negflag;
    int nb4 = (cnt + 3) >> 2;
    int4 q = (nb4 > 0) ? __ldg(&bucket4[0]) : make_int4(node, node, node, node);

#define GATH_BODY(DOMIN)                                                        \
    for (int c = 0; c < nb4; c++) {                                             \
        int4 qn = (c + 1 < nb4) ? __ldg(&bucket4[c + 1]) : q;                   \
        int j0 = 4 * c;                                                         \
        int s0 = (j0 + 0 < cnt) ? q.x : node;                                   \
        int s1 = (j0 + 1 < cnt) ? q.y : node;                                   \
        int s2 = (j0 + 2 < cnt) ? q.z : node;                                   \
        int s3 = (j0 + 3 < cnt) ? q.w : node;                                   \
        uint4 u0 = __ldg(&h8[(ll)s0 * 8 + l]);                                  \
        uint4 u1 = __ldg(&h8[(ll)s1 * 8 + l]);                                  \
        uint4 u2 = __ldg(&h8[(ll)s2 * 8 + l]);                                  \
        uint4 u3 = __ldg(&h8[(ll)s3 * 8 + l]);                                  \
        const uint4* us[4] = {&u0, &u1, &u2, &u3};                              \
        _Pragma("unroll")                                                       \
        for (int t = 0; t < 4; t++) {                                           \
            __half2 a0 = *reinterpret_cast<const __half2*>(&us[t]->x);          \
            __half2 a1 = *reinterpret_cast<const __half2*>(&us[t]->y);          \
            __half2 a2 = *reinterpret_cast<const __half2*>(&us[t]->z);          \
            __half2 a3 = *reinterpret_cast<const __half2*>(&us[t]->w);          \
            mx0 = __hmax2(mx0, a0); mx1 = __hmax2(mx1, a1);                     \
            mx2 = __hmax2(mx2, a2); mx3 = __hmax2(mx3, a3);                     \
            if (DOMIN) {                                                        \
                mn0 = __hmin2(mn0, a0); mn1 = __hmin2(mn1, a1);                 \
                mn2 = __hmin2(mn2, a2); mn3 = __hmin2(mn3, a3);                 \
            }                                                                   \
        }                                                                       \
        q = qn;                                                                 \
    }

    if (!neg) { GATH_BODY(0) } else { GATH_BODY(1) }
#undef GATH_BODY

    float4 sca = *reinterpret_cast<const float4*>(&g_scale[8 * l]);
    float4 scb = *reinterpret_cast<const float4*>(&g_scale[8 * l + 4]);
    float4 sha = *reinterpret_cast<const float4*>(&g_shift[8 * l]);
    float4 shb = *reinterpret_cast<const float4*>(&g_shift[8 * l + 4]);

    float2 fx0 = __half22float2(mx0), fx1 = __half22float2(mx1);
    float2 fx2 = __half22float2(mx2), fx3 = __half22float2(mx3);

    float a0, a1, a2, a3, a4, a5, a6, a7;
    if (!neg) {
        a0 = fmaxf(fmaf(fx0.x, sca.x, sha.x), 0.f);
        a1 = fmaxf(fmaf(fx0.y, sca.y, sha.y), 0.f);
        a2 = fmaxf(fmaf(fx1.x, sca.z, sha.z), 0.f);
        a3 = fmaxf(fmaf(fx1.y, sca.w, sha.w), 0.f);
        a4 = fmaxf(fmaf(fx2.x, scb.x, shb.x), 0.f);
        a5 = fmaxf(fmaf(fx2.y, scb.y, shb.y), 0.f);
        a6 = fmaxf(fmaf(fx3.x, scb.z, shb.z), 0.f);
        a7 = fmaxf(fmaf(fx3.y, scb.w, shb.w), 0.f);
    } else {
        float2 fn0 = __half22float2(mn0), fn1 = __half22float2(mn1);
        float2 fn2 = __half22float2(mn2), fn3 = __half22float2(mn3);
        a0 = fmaxf(fmaxf(fmaf(fx0.x, sca.x, sha.x), fmaf(fn0.x, sca.x, sha.x)), 0.f);
        a1 = fmaxf(fmaxf(fmaf(fx0.y, sca.y, sha.y), fmaf(fn0.y, sca.y, sha.y)), 0.f);
        a2 = fmaxf(fmaxf(fmaf(fx1.x, sca.z, sha.z), fmaf(fn1.x, sca.z, sha.z)), 0.f);
        a3 = fmaxf(fmaxf(fmaf(fx1.y, sca.w, sha.w), fmaf(fn1.y, sca.w, sha.w)), 0.f);
        a4 = fmaxf(fmaxf(fmaf(fx2.x, scb.x, shb.x), fmaf(fn2.x, scb.x, shb.x)), 0.f);
        a5 = fmaxf(fmaxf(fmaf(fx2.y, scb.y, shb.y), fmaf(fn2.y, scb.y, shb.y)), 0.f);
        a6 = fmaxf(fmaxf(fmaf(fx3.x, scb.z, shb.z), fmaf(fn3.x, scb.z, shb.z)), 0.f);
        a7 = fmaxf(fmaxf(fmaf(fx3.y, scb.w, shb.w), fmaf(fn3.y, scb.w, shb.w)), 0.f);
    }

    float* xbase = &g_xsum[(ll)vox * 64 + 8 * l];
    asm volatile("red.global.add.v4.f32 [%0], {%1, %2, %3, %4};"
                 :: "l"(xbase), "f"(a0), "f"(a1), "f"(a2), "f"(a3) : "memory");
    asm volatile("red.global.add.v4.f32 [%0], {%1, %2, %3, %4};"
                 :: "l"(xbase + 4), "f"(a4), "f"(a5), "f"(a6), "f"(a7) : "memory");
    if (l == 0) {
        atomicAdd(&g_cnt[vox], 1.0f);
        atomicAdd(&g_psum[vox * 3 + 0], px);
        atomicAdd(&g_psum[vox * 3 + 1], py);
        atomicAdd(&g_psum[vox * 3 + 2], pz);
    }
}

// -------- finalize output [NVOX, 67] AND self-clean all accumulators for next replay ----
__global__ __launch_bounds__(256) void out_kernel(float* __restrict__ out) {
    int gid = blockIdx.x * blockDim.x + threadIdx.x;     // 262144 threads
    g_cnt_i[gid] = 0;

    int vox = gid >> 5;
    int lane = gid & 31;
    if (vox >= NVOX) return;

    float cntv = g_cnt[vox];
    float inv = 1.0f / fmaxf(cntv, 1.0f);

    float v0 = g_xsum[vox * 64 + lane];
    float v1 = g_xsum[vox * 64 + 32 + lane];
    float p = (lane < 3) ? g_psum[vox * 3 + lane] : 0.f;

    out[(ll)vox * 67 + lane] = v0 * inv;
    out[(ll)vox * 67 + 32 + lane] = v1 * inv;
    if (lane < 3) out[(ll)vox * 67 + 64 + lane] = p * inv;

    __syncwarp();
    g_xsum[vox * 64 + lane] = 0.f;
    g_xsum[vox * 64 + 32 + lane] = 0.f;
    if (lane < 3) g_psum[vox * 3 + lane] = 0.f;
    if (lane == 0) g_cnt[vox] = 0.f;
}

extern "C" void kernel_launch(void* const* d_in, const int* in_sizes, int n_in,
                              void* d_out, int out_size) {
    const float* x     = (const float*)d_in[0];  // [N, 64]
    const float* pos   = (const float*)d_in[1];  // [N, 3]
    const int*   ei    = (const int*)d_in[2];    // [2, E]
    const float* W     = (const float*)d_in[3];  // [64, 64]
    const float* b     = (const float*)d_in[4];  // [64]
    const float* gamma = (const float*)d_in[5];  // [64]
    const float* beta  = (const float*)d_in[6];  // [64]
    float* out = (float*)d_out;                  // [8000, 67]

    // Single stream, 5 launches. Fat kernel fuses GEMM+stats with the edge
    // bucket build (disjoint resources, hardware-coscheduled).
    fat_kernel<<<FAT_BLOCKS, 256, GS_SMEM_BYTES>>>(x, W, b, ei);       // 1
    scale_kernel<<<1, 64>>>(gamma, beta);                              // 2
    gather_kernel<<<NN * 8 / 256 / 2, 256>>>(pos, 0);                  // 3
    gather_kernel<<<NN * 8 / 256 / 2, 256>>>(pos, NN / 2);             // 4 <- ncu slot
    out_kernel<<<NN / 256, 256>>>(out);                                // 5
}

// round 14
// speedup vs baseline: 1.1052x; 1.1045x over previous
#include <cuda_runtime.h>
#include <cuda_fp16.h>
#include <mma.h>
#include <stdint.h>

using namespace nvcuda;

// Problem constants
#define NN 262144
#define EE (NN * 16)
#define CC 64
#define NVOXD 20
#define NVOX 8000
#define BN_EPS 1e-5f
#define GRID_INV 2.0f   // 1/0.5
#define FULLMASK 0xFFFFFFFFu
#define MAXDEG 64

typedef unsigned long long ull;
typedef long long ll;

// -------- scratch (all load-time zero; out_kernel re-zeroes accumulators each replay) ----
__device__ __half g_hh[NN * CC];          // h = x@W+b in fp16
__device__ float g_colsum[CC];
__device__ float g_colsq[CC];
__device__ float g_scale[CC];
__device__ float g_shift[CC];
__device__ int   g_negflag;               // any(scale<0)?
__device__ float g_xsum[NVOX * CC];
__device__ float g_psum[NVOX * 3];
__device__ float g_cnt[NVOX];
__device__ int   g_cnt_i[NN];             // in-degree
__device__ int   g_adj[NN * MAXDEG + 4];  // fixed-capacity buckets

// ======================= FAT kernel: wmma GEMM+stats blocks + scatter blocks =======================
// 18432 blocks: blockIdx%9==0 -> GEMM block (2048), else scatter block (16384).
// Interleaving co-schedules both workloads on every SM: GEMM is tensor/smem/DRAM-read
// bound, scatter is L2-atomic bound -> near-disjoint resources.
#define XS 80
#define WS 80
#define CSO 72
#define SM_X_BYTES (128 * XS * 2)
#define SM_W_OFF   SM_X_BYTES
#define SM_C_BYTES (128 * CSO * 4)
#define SM_RED_OFF SM_C_BYTES
#define GS_SMEM_BYTES (SM_C_BYTES + 512)
#define GEMM_BLOCKS (NN / 128)            // 2048
#define SCAT_BLOCKS (EE / 256)            // 16384
#define FAT_BLOCKS (GEMM_BLOCKS + SCAT_BLOCKS)   // 18432 = 2048*9

__device__ __forceinline__ void gemm_body(int gb, const float* __restrict__ x,
                                          const float* __restrict__ W,
                                          const float* __restrict__ b,
                                          char* smc) {
    __half* xs  = reinterpret_cast<__half*>(smc);
    __half* Wsf = reinterpret_cast<__half*>(smc + SM_W_OFF);
    float*  Cs  = reinterpret_cast<float*>(smc);
    float*  red = reinterpret_cast<float*>(smc + SM_RED_OFF);
    int tid = threadIdx.x;
    int row0 = gb * 128;

#pragma unroll
    for (int i = tid; i < 2048; i += 256) {
        int row = i >> 4, c4 = (i & 15) * 4;
        float4 v = __ldcs(&reinterpret_cast<const float4*>(x + (ll)(row0 + row) * 64)[i & 15]);
        __half2 lo = __floats2half2_rn(v.x, v.y);
        __half2 hi = __floats2half2_rn(v.z, v.w);
        uint2 p;
        p.x = *reinterpret_cast<unsigned*>(&lo);
        p.y = *reinterpret_cast<unsigned*>(&hi);
        *reinterpret_cast<uint2*>(&xs[row * XS + c4]) = p;
    }
#pragma unroll
    for (int i = tid; i < 1024; i += 256) {
        int row = i >> 4, c4 = (i & 15) * 4;
        float4 v = reinterpret_cast<const float4*>(W)[i];
        __half2 lo = __floats2half2_rn(v.x, v.y);
        __half2 hi = __floats2half2_rn(v.z, v.w);
        uint2 p;
        p.x = *reinterpret_cast<unsigned*>(&lo);
        p.y = *reinterpret_cast<unsigned*>(&hi);
        *reinterpret_cast<uint2*>(&Wsf[row * WS + c4]) = p;
    }
    __syncthreads();

    int w = tid >> 5;
    wmma::fragment<wmma::accumulator, 16, 16, 16, float> acc[4];
#pragma unroll
    for (int n = 0; n < 4; n++) wmma::fill_fragment(acc[n], 0.0f);
#pragma unroll
    for (int k = 0; k < 4; k++) {
        wmma::fragment<wmma::matrix_a, 16, 16, 16, __half, wmma::row_major> af;
        wmma::load_matrix_sync(af, xs + (16 * w) * XS + 16 * k, XS);
#pragma unroll
        for (int n = 0; n < 4; n++) {
            wmma::fragment<wmma::matrix_b, 16, 16, 16, __half, wmma::row_major> bf;
            wmma::load_matrix_sync(bf, Wsf + (16 * k) * WS + 16 * n, WS);
            wmma::mma_sync(acc[n], af, bf, acc[n]);
        }
    }
    __syncthreads();

#pragma unroll
    for (int n = 0; n < 4; n++)
        wmma::store_matrix_sync(Cs + (16 * w) * CSO + 16 * n, acc[n], CSO, wmma::mem_row_major);
    if (tid < 128) red[tid] = 0.f;
    __syncthreads();

    int cp = tid & 31;
    int rg = tid >> 5;
    float b0 = b[2 * cp], b1 = b[2 * cp + 1];
    float s0 = 0.f, q0 = 0.f, s1 = 0.f, q1 = 0.f;
    unsigned* hout = reinterpret_cast<unsigned*>(g_hh);
#pragma unroll
    for (int rr = 0; rr < 16; rr++) {
        int row = 16 * rg + rr;
        float2 v = *reinterpret_cast<float2*>(&Cs[row * CSO + 2 * cp]);
        float v0 = v.x + b0, v1 = v.y + b1;
        __half2 h2 = __floats2half2_rn(v0, v1);
        hout[(ll)(row0 + row) * 32 + cp] = *reinterpret_cast<unsigned*>(&h2);
        s0 += v0; q0 += v0 * v0; s1 += v1; q1 += v1 * v1;
    }
    atomicAdd(&red[2 * cp], s0);      atomicAdd(&red[2 * cp + 1], s1);
    atomicAdd(&red[64 + 2 * cp], q0); atomicAdd(&red[64 + 2 * cp + 1], q1);
    __syncthreads();
    if (tid < 64) {
        atomicAdd(&g_colsum[tid], red[tid]);
        atomicAdd(&g_colsq[tid],  red[64 + tid]);
    }
}

__device__ __forceinline__ void scatter_body(int sb, const int* __restrict__ ei) {
    int e = sb * 256 + threadIdx.x;
    int row = __ldcs(&ei[e]);
    int col = __ldcs(&ei[EE + e]);
    int p = atomicAdd(&g_cnt_i[col], 1);
    if (p < MAXDEG) g_adj[col * MAXDEG + p] = row;
}

__global__ __launch_bounds__(256) void fat_kernel(const float* __restrict__ x,
                                                  const float* __restrict__ W,
                                                  const float* __restrict__ b,
                                                  const int* __restrict__ ei) {
    extern __shared__ char smc[];
    int r = blockIdx.x % 9;
    int g = blockIdx.x / 9;
    if (r == 0) gemm_body(g, x, W, b, smc);
    else        scatter_body(g * 8 + (r - 1), ei);
}

// -------- fold BN into scale/shift; detect negative scales; reset stats --------
__global__ void scale_kernel(const float* __restrict__ gamma, const float* __restrict__ beta) {
    __shared__ int flag;
    int c = threadIdx.x;
    if (c == 0) flag = 0;
    __syncthreads();
    if (c < CC) {
        float mean = g_colsum[c] * (1.0f / NN);
        float var = g_colsq[c] * (1.0f / NN) - mean * mean;
        float sc = gamma[c] * rsqrtf(var + BN_EPS);
        g_scale[c] = sc;
        g_shift[c] = beta[c] - mean * sc;
        g_colsum[c] = 0.f;
        g_colsq[c] = 0.f;
        if (sc < 0.f) flag = 1;
    }
    __syncthreads();
    if (c == 0) g_negflag = flag;
}

// ======================= gather (R11 form, SINGLE full grid) -> out =======================
// 8 lanes per node; lane handles 8 channels (uint4). Neighbor indices from uniform
// int4 loads, prefetched one chunk ahead; bounds handled by selects.
__global__ __launch_bounds__(256, 5) void gather_kernel(const float* __restrict__ pos) {
    int node = (blockIdx.x * blockDim.x + threadIdx.x) >> 3;
    int l = threadIdx.x & 7;
    int base8 = threadIdx.x & 24;
    unsigned int m8 = 0xFFu << base8;

    int cnt = min(g_cnt_i[node], MAXDEG);
    const int4* bucket4 = reinterpret_cast<const int4*>(&g_adj[(ll)node * MAXDEG]);
    float px = 0.f, py = 0.f, pz = 0.f;
    if (l == 0) {
        px = pos[node * 3 + 0];
        py = pos[node * 3 + 1];
        pz = pos[node * 3 + 2];
    }
    const uint4* h8 = reinterpret_cast<const uint4*>(g_hh);
    uint4 self = __ldg(&h8[(ll)node * 8 + l]);

    __half2 mx0 = *reinterpret_cast<__half2*>(&self.x);
    __half2 mx1 = *reinterpret_cast<__half2*>(&self.y);
    __half2 mx2 = *reinterpret_cast<__half2*>(&self.z);
    __half2 mx3 = *reinterpret_cast<__half2*>(&self.w);
    __half2 mn0 = mx0, mn1 = mx1, mn2 = mx2, mn3 = mx3;

    int vox = 0;
    if (l == 0) {
        int vx = min(max((int)floorf(px * GRID_INV), 0), NVOXD - 1);
        int vy = min(max((int)floorf(py * GRID_INV), 0), NVOXD - 1);
        int vz = min(max((int)floorf(pz * GRID_INV), 0), NVOXD - 1);
        vox = (vx * NVOXD + vy) * NVOXD + vz;
    }
    vox = __shfl_sync(m8, vox, base8);

    int neg = g_negflag;
    int nb4 = (cnt + 3) >> 2;
    int4 q = (nb4 > 0) ? __ldg(&bucket4[0]) : make_int4(node, node, node, node);

#define GATH_BODY(DOMIN)                                                        \
    for (int c = 0; c < nb4; c++) {                                             \
        int4 qn = (c + 1 < nb4) ? __ldg(&bucket4[c + 1]) : q;                   \
        int j0 = 4 * c;                                                         \
        int s0 = (j0 + 0 < cnt) ? q.x : node;                                   \
        int s1 = (j0 + 1 < cnt) ? q.y : node;                                   \
        int s2 = (j0 + 2 < cnt) ? q.z : node;                                   \
        int s3 = (j0 + 3 < cnt) ? q.w : node;                                   \
        uint4 u0 = __ldg(&h8[(ll)s0 * 8 + l]);                                  \
        uint4 u1 = __ldg(&h8[(ll)s1 * 8 + l]);                                  \
        uint4 u2 = __ldg(&h8[(ll)s2 * 8 + l]);                                  \
        uint4 u3 = __ldg(&h8[(ll)s3 * 8 + l]);                                  \
        const uint4* us[4] = {&u0, &u1, &u2, &u3};                              \
        _Pragma("unroll")                                                       \
        for (int t = 0; t < 4; t++) {                                           \
            __half2 a0 = *reinterpret_cast<const __half2*>(&us[t]->x);          \
            __half2 a1 = *reinterpret_cast<const __half2*>(&us[t]->y);          \
            __half2 a2 = *reinterpret_cast<const __half2*>(&us[t]->z);          \
            __half2 a3 = *reinterpret_cast<const __half2*>(&us[t]->w);          \
            mx0 = __hmax2(mx0, a0); mx1 = __hmax2(mx1, a1);                     \
            mx2 = __hmax2(mx2, a2); mx3 = __hmax2(mx3, a3);                     \
            if (DOMIN) {                                                        \
                mn0 = __hmin2(mn0, a0); mn1 = __hmin2(mn1, a1);                 \
                mn2 = __hmin2(mn2, a2); mn3 = __hmin2(mn3, a3);                 \
            }                                                                   \
        }                                                                       \
        q = qn;                                                                 \
    }

    if (!neg) { GATH_BODY(0) } else { GATH_BODY(1) }
#undef GATH_BODY

    float4 sca = *reinterpret_cast<const float4*>(&g_scale[8 * l]);
    float4 scb = *reinterpret_cast<const float4*>(&g_scale[8 * l + 4]);
    float4 sha = *reinterpret_cast<const float4*>(&g_shift[8 * l]);
    float4 shb = *reinterpret_cast<const float4*>(&g_shift[8 * l + 4]);

    float2 fx0 = __half22float2(mx0), fx1 = __half22float2(mx1);
    float2 fx2 = __half22float2(mx2), fx3 = __half22float2(mx3);

    float a0, a1, a2, a3, a4, a5, a6, a7;
    if (!neg) {
        a0 = fmaxf(fmaf(fx0.x, sca.x, sha.x), 0.f);
        a1 = fmaxf(fmaf(fx0.y, sca.y, sha.y), 0.f);
        a2 = fmaxf(fmaf(fx1.x, sca.z, sha.z), 0.f);
        a3 = fmaxf(fmaf(fx1.y, sca.w, sha.w), 0.f);
        a4 = fmaxf(fmaf(fx2.x, scb.x, shb.x), 0.f);
        a5 = fmaxf(fmaf(fx2.y, scb.y, shb.y), 0.f);
        a6 = fmaxf(fmaf(fx3.x, scb.z, shb.z), 0.f);
        a7 = fmaxf(fmaf(fx3.y, scb.w, shb.w), 0.f);
    } else {
        float2 fn0 = __half22float2(mn0), fn1 = __half22float2(mn1);
        float2 fn2 = __half22float2(mn2), fn3 = __half22float2(mn3);
        a0 = fmaxf(fmaxf(fmaf(fx0.x, sca.x, sha.x), fmaf(fn0.x, sca.x, sha.x)), 0.f);
        a1 = fmaxf(fmaxf(fmaf(fx0.y, sca.y, sha.y), fmaf(fn0.y, sca.y, sha.y)), 0.f);
        a2 = fmaxf(fmaxf(fmaf(fx1.x, sca.z, sha.z), fmaf(fn1.x, sca.z, sha.z)), 0.f);
        a3 = fmaxf(fmaxf(fmaf(fx1.y, sca.w, sha.w), fmaf(fn1.y, sca.w, sha.w)), 0.f);
        a4 = fmaxf(fmaxf(fmaf(fx2.x, scb.x, shb.x), fmaf(fn2.x, scb.x, shb.x)), 0.f);
        a5 = fmaxf(fmaxf(fmaf(fx2.y, scb.y, shb.y), fmaf(fn2.y, scb.y, shb.y)), 0.f);
        a6 = fmaxf(fmaxf(fmaf(fx3.x, scb.z, shb.z), fmaf(fn3.x, scb.z, shb.z)), 0.f);
        a7 = fmaxf(fmaxf(fmaf(fx3.y, scb.w, shb.w), fmaf(fn3.y, scb.w, shb.w)), 0.f);
    }

    float* xbase = &g_xsum[(ll)vox * 64 + 8 * l];
    asm volatile("red.global.add.v4.f32 [%0], {%1, %2, %3, %4};"
                 :: "l"(xbase), "f"(a0), "f"(a1), "f"(a2), "f"(a3) : "memory");
    asm volatile("red.global.add.v4.f32 [%0], {%1, %2, %3, %4};"
                 :: "l"(xbase + 4), "f"(a4), "f"(a5), "f"(a6), "f"(a7) : "memory");
    if (l == 0) {
        atomicAdd(&g_cnt[vox], 1.0f);
        atomicAdd(&g_psum[vox * 3 + 0], px);
        atomicAdd(&g_psum[vox * 3 + 1], py);
        atomicAdd(&g_psum[vox * 3 + 2], pz);
    }
}

// -------- finalize output [NVOX, 67] AND self-clean all accumulators for next replay ----
__global__ __launch_bounds__(256) void out_kernel(float* __restrict__ out) {
    int gid = blockIdx.x * blockDim.x + threadIdx.x;     // 262144 threads
    g_cnt_i[gid] = 0;

    int vox = gid >> 5;
    int lane = gid & 31;
    if (vox >= NVOX) return;

    float cntv = g_cnt[vox];
    float inv = 1.0f / fmaxf(cntv, 1.0f);

    float v0 = g_xsum[vox * 64 + lane];
    float v1 = g_xsum[vox * 64 + 32 + lane];
    float p = (lane < 3) ? g_psum[vox * 3 + lane] : 0.f;

    out[(ll)vox * 67 + lane] = v0 * inv;
    out[(ll)vox * 67 + 32 + lane] = v1 * inv;
    if (lane < 3) out[(ll)vox * 67 + 64 + lane] = p * inv;

    __syncwarp();
    g_xsum[vox * 64 + lane] = 0.f;
    g_xsum[vox * 64 + 32 + lane] = 0.f;
    if (lane < 3) g_psum[vox * 3 + lane] = 0.f;
    if (lane == 0) g_cnt[vox] = 0.f;
}

extern "C" void kernel_launch(void* const* d_in, const int* in_sizes, int n_in,
                              void* d_out, int out_size) {
    const float* x     = (const float*)d_in[0];  // [N, 64]
    const float* pos   = (const float*)d_in[1];  // [N, 3]
    const int*   ei    = (const int*)d_in[2];    // [2, E]
    const float* W     = (const float*)d_in[3];  // [64, 64]
    const float* b     = (const float*)d_in[4];  // [64]
    const float* gamma = (const float*)d_in[5];  // [64]
    const float* beta  = (const float*)d_in[6];  // [64]
    float* out = (float*)d_out;                  // [8000, 67]

    // Single stream, 4 launches. Fat kernel fuses GEMM+stats with the edge
    // bucket build (disjoint resources, hardware-coscheduled); gather is one
    // full-grid launch (half-grid split in R13 cost ~20 us of tail effects).
    fat_kernel<<<FAT_BLOCKS, 256, GS_SMEM_BYTES>>>(x, W, b, ei);       // 1
    scale_kernel<<<1, 64>>>(gamma, beta);                              // 2
    gather_kernel<<<NN * 8 / 256, 256>>>(pos);                         // 3
    out_kernel<<<NN / 256, 256>>>(out);                                // 4
}